// round 16
// baseline (speedup 1.0000x reference)
#include <cuda_runtime.h>
#include <cuda_bf16.h>
#include <cstdint>

#define THREADS 512
#define ATTNW_SHIFT 20.0f
#define INV_SQRT_D  0.17677669529663687f
#define SQRT3       1.7320508075688772f
#define SQRT32      5.656854249492381f
#define L2E         1.4426950408889634f

// word(=float)-index smem layout
#define WG2H  0        // 128*20
#define WG2L  2560
#define WWTH  5120     // 384*20 (reused as RBUF after head loop)
#define WWTL  12800
#define WPHH  20480    // 128*36 (Q words 0-15, K words 16-31)
#define WPHL  25088
#define WCTH  29696    // 32*68 C^T
#define WCTL  31872
#define F_H2SW4 34048  // float4[128]
#define F_BH   34560
#define F_WEQ  34592
#define F_PART 34600   // 128*2 row-sum partials
#define F_H2WH 34856   // 4 heads * 3 rows * 68
#define F_H2WL 35672
#define F_RQK  36488   // init-only scratch
#define F_RWV  44680
#define F_RWH  48776
#define SMEM_BYTES 211488
#define RBUF  WWTH
#define OFFPH 18432    // bytes WPHL-WPHH
#define OFFCT 8704     // bytes WCTL-WCTH
#define OFFH2 3264     // bytes F_H2WL-F_H2WH

static __device__ __forceinline__ uint32_t smem_u32(const void* p) {
    uint32_t a;
    asm("{ .reg .u64 t; cvta.to.shared.u64 t, %1; cvt.u32.u64 %0, t; }" : "=r"(a) : "l"(p));
    return a;
}
static __device__ __forceinline__ uint32_t packb(float e0, float e1) {
    uint32_t r;
    asm("cvt.rn.bf16x2.f32 %0, %1, %2;" : "=r"(r) : "f"(e1), "f"(e0));
    return r;
}
static __device__ __forceinline__ void pack_hl(float v0, float v1,
                                               uint32_t& h, uint32_t& l) {
    h = packb(v0, v1);
    float h0 = __uint_as_float(h << 16);
    float h1 = __uint_as_float(h & 0xFFFF0000u);
    l = packb(v0 - h0, v1 - h1);
}
static __device__ __forceinline__ float ex2a(float x) {
    float r; asm("ex2.approx.f32 %0, %1;" : "=f"(r) : "f"(x)); return r;
}
static __device__ __forceinline__ void mma16(float* d, uint32_t a0, uint32_t a1,
                                             uint32_t a2, uint32_t a3,
                                             uint32_t b0, uint32_t b1) {
    asm volatile("mma.sync.aligned.m16n8k16.row.col.f32.bf16.bf16.f32 "
                 "{%0,%1,%2,%3}, {%4,%5,%6,%7}, {%8,%9}, {%0,%1,%2,%3};"
                 : "+f"(d[0]), "+f"(d[1]), "+f"(d[2]), "+f"(d[3])
                 : "r"(a0), "r"(a1), "r"(a2), "r"(a3), "r"(b0), "r"(b1));
}
static __device__ __forceinline__ void mma3(float* d, const uint32_t* ah,
                                            const uint32_t* al,
                                            uint32_t bh0, uint32_t bh1,
                                            uint32_t bl0, uint32_t bl1) {
    mma16(d, ah[0], ah[1], ah[2], ah[3], bh0, bh1);
    mma16(d, al[0], al[1], al[2], al[3], bh0, bh1);
    mma16(d, ah[0], ah[1], ah[2], ah[3], bl0, bl1);
}
static __device__ __forceinline__ void afrag_from_acc(const float* acc0, const float* acc1,
                                                      float s0, float s1,
                                                      uint32_t* ah, uint32_t* al) {
    pack_hl(acc0[0] * s0, acc0[1] * s0, ah[0], al[0]);
    pack_hl(acc0[2] * s1, acc0[3] * s1, ah[1], al[1]);
    pack_hl(acc1[0] * s0, acc1[1] * s0, ah[2], al[2]);
    pack_hl(acc1[2] * s1, acc1[3] * s1, ah[3], al[3]);
}
#define LDSM4(r, ba) \
    asm volatile("ldmatrix.sync.aligned.m8n8.x4.shared.b16 {%0,%1,%2,%3}, [%4];" \
                 : "=r"((r)[0]), "=r"((r)[1]), "=r"((r)[2]), "=r"((r)[3]) : "r"(ba))
#define LDSM2(r, ba) \
    asm volatile("ldmatrix.sync.aligned.m8n8.x2.shared.b16 {%0,%1}, [%2];" \
                 : "=r"((r)[0]), "=r"((r)[1]) : "r"(ba))
#define STSM4(ba, r0, r1, r2, r3) \
    asm volatile("stmatrix.sync.aligned.m8n8.x4.shared.b16 [%0], {%1,%2,%3,%4};" \
                 :: "r"(ba), "r"(r0), "r"(r1), "r"(r2), "r"(r3))
#define STSM2T(ba, r0, r1) \
    asm volatile("stmatrix.sync.aligned.m8n8.x2.trans.shared.b16 [%0], {%1,%2};" \
                 :: "r"(ba), "r"(r0), "r"(r1))

__global__ void __launch_bounds__(THREADS, 1)
rep_bf16_kernel(const float* __restrict__ g2, const float* __restrict__ h2,
                const float* __restrict__ sw, const float* __restrict__ wqk,
                const float* __restrict__ wv, const float* __restrict__ wh,
                const float* __restrict__ bh, const float* __restrict__ weq,
                const int* __restrict__ mask, float* __restrict__ outg,
                float* __restrict__ outh)
{
    extern __shared__ __align__(16) float smf[];
    uint32_t* smu = (uint32_t*)smf;
    const uint32_t sb = smem_u32(smf);
    const int tid = threadIdx.x, w = tid >> 5, lane = tid & 31;
    const int g = lane >> 2, t = lane & 3;
    const int loc = blockIdx.x;
    const int r8 = lane & 7, s01 = (lane >> 3) & 1, s2 = lane >> 4;
    const int wm = w >> 1, wn = w & 1;
    const int m0 = wm * 16;

    const float* g2l = g2 + (size_t)loc * 128 * 32;
    const float* h2l = h2 + (size_t)loc * 128 * 3;
    const float* swl = sw + (size_t)loc * 128;
    const int*   ml  = mask + (size_t)loc * 128;

    // ---- stage raw weights ----
    {
        const float4* s1 = (const float4*)wqk;
        float4* d1 = (float4*)(smf + F_RQK);
        #pragma unroll
        for (int i = 0; i < 4; ++i) d1[tid + i * 512] = s1[tid + i * 512];
        const float4* s2p = (const float4*)wv;
        float4* d2 = (float4*)(smf + F_RWV);
        #pragma unroll
        for (int i = 0; i < 2; ++i) d2[tid + i * 512] = s2p[tid + i * 512];
        const float4* s3 = (const float4*)wh;
        float4* d3 = (float4*)(smf + F_RWH);
        #pragma unroll
        for (int i = 0; i < 2; ++i) d3[tid + i * 512] = s3[tid + i * 512];
    }
    // ---- g2 -> bf16 hi/lo (threads 0-255) ----
    if (tid < 256) {
        int r = tid >> 1, hf = tid & 1;
        const float* src = g2l + (size_t)r * 32 + hf * 16;
        float e[16];
        #pragma unroll
        for (int i = 0; i < 4; ++i) {
            float4 v = ((const float4*)src)[i];
            e[4*i] = v.x; e[4*i+1] = v.y; e[4*i+2] = v.z; e[4*i+3] = v.w;
        }
        #pragma unroll
        for (int j = 0; j < 8; ++j) {
            uint32_t hu, lu;
            pack_hl(e[2*j], e[2*j+1], hu, lu);
            smu[WG2H + r * 20 + hf * 8 + j] = hu;
            smu[WG2L + r * 20 + hf * 8 + j] = lu;
        }
    }
    if (tid < 128) {
        float a = h2l[tid * 3], b = h2l[tid * 3 + 1], c = h2l[tid * 3 + 2];
        float sv = swl[tid];
        ((float4*)(smf + F_H2SW4))[tid] = make_float4(a, b, c, ml[tid] ? sv : -sv);
    }
    if (tid < 32) smf[F_BH + tid] = bh[tid];
    if (tid < 4)  smf[F_WEQ + tid] = weq[tid];
    __syncthreads();

    // ---- WallT Q/K rows (remapped lanes: consecutive rqk per warp) ----
    #pragma unroll
    for (int it = 0; it < 8; ++it) {
        int i = tid + it * 512;
        int rqk = i & 255, j = i >> 8;
        int hh = rqk >> 6, r = rqk & 63;
        int c = hh * 96 + r;
        int src = (r < 32) ? r * 8 + hh : (r - 32) * 8 + 4 + hh;
        float v0 = smf[F_RQK + (2 * j) * 256 + src];
        float v1 = smf[F_RQK + (2 * j + 1) * 256 + src];
        uint32_t hu, lu;
        pack_hl(v0, v1, hu, lu);
        smu[WWTH + c * 20 + j] = hu;
        smu[WWTL + c * 20 + j] = lu;
    }
    // ---- WallT C rows: wc = wv @ wh, all 512 threads, 4 ILP chains ----
    {
        int hh = tid >> 7;            // 0..3
        int m  = (tid >> 2) & 31;     // 0..31
        int kq = tid & 3;             // k quarter
        float whcol[32];
        #pragma unroll 8
        for (int gg = 0; gg < 32; ++gg)
            whcol[gg] = smf[F_RWH + (gg * 4 + hh) * 32 + m];
        int c = hh * 96 + 64 + m;
        #pragma unroll
        for (int jj = 0; jj < 4; ++jj) {
            int k0 = kq * 8 + jj * 2;
            const float* wv0 = smf + F_RWV + k0 * 128 + hh;
            const float* wv1 = wv0 + 128;
            float s0a = 0.f, s0b = 0.f, s1a = 0.f, s1b = 0.f;
            #pragma unroll
            for (int gg = 0; gg < 32; gg += 2) {
                s0a = fmaf(wv0[gg * 4],     whcol[gg],     s0a);
                s0b = fmaf(wv0[gg * 4 + 4], whcol[gg + 1], s0b);
                s1a = fmaf(wv1[gg * 4],     whcol[gg],     s1a);
                s1b = fmaf(wv1[gg * 4 + 4], whcol[gg + 1], s1b);
            }
            uint32_t hu, lu;
            pack_hl(s0a + s0b, s1a + s1b, hu, lu);
            smu[WWTH + c * 20 + kq * 4 + jj] = hu;
            smu[WWTL + c * 20 + kq * 4 + jj] = lu;
        }
    }
    // ---- H2W: all 4 heads' h2*weq rows (read during GEMM_O) ----
    if (tid < 256) {
        int hh = tid >> 6, idx = tid & 63;
        float wqh = smf[F_WEQ + hh];
        float4 ha = ((float4*)(smf + F_H2SW4))[2 * idx];
        float4 hb = ((float4*)(smf + F_H2SW4))[2 * idx + 1];
        uint32_t hu, lu;
        pack_hl(ha.x * wqh, hb.x * wqh, hu, lu);
        smu[F_H2WH + (hh * 3 + 0) * 68 + idx] = hu;
        smu[F_H2WL + (hh * 3 + 0) * 68 + idx] = lu;
        pack_hl(ha.y * wqh, hb.y * wqh, hu, lu);
        smu[F_H2WH + (hh * 3 + 1) * 68 + idx] = hu;
        smu[F_H2WL + (hh * 3 + 1) * 68 + idx] = lu;
        pack_hl(ha.z * wqh, hb.z * wqh, hu, lu);
        smu[F_H2WH + (hh * 3 + 2) * 68 + idx] = hu;
        smu[F_H2WL + (hh * 3 + 2) * 68 + idx] = lu;
    }
    __syncthreads();

    // ---- persistent state ----
    float oacc[5][4];
    #pragma unroll
    for (int a = 0; a < 5; ++a)
        #pragma unroll
        for (int b = 0; b < 4; ++b) oacc[a][b] = 0.f;
    float rswm[2], rh2I[2][3], rwL[2];
    #pragma unroll
    for (int d = 0; d < 2; ++d) {
        int row = m0 + d * 8 + g;
        float4 rH = ((float4*)(smf + F_H2SW4))[row];
        rh2I[d][0] = rH.x * INV_SQRT_D;
        rh2I[d][1] = rH.y * INV_SQRT_D;
        rh2I[d][2] = rH.z * INV_SQRT_D;
        rwL[d] = fabsf(rH.w) * L2E;
        rswm[d] = fmaxf(rH.w, 0.f);
    }

    // lane-address bases (byte addrs)
    const int arow = m0 + r8 + s01 * 8;
    const uint32_t aG2h = sb + 4 * (WG2H + arow * 20 + s2 * 4);
    const uint32_t aG2l = sb + 4 * (WG2L + arow * 20 + s2 * 4);
    const uint32_t aPHh = sb + 4 * (WPHH + arow * 36 + s2 * 4);
    const uint32_t stPH = aPHh;
    const uint32_t stCT = sb + 4 * (WCTH + r8 * 68 + wm * 8 + s01 * 4);
    const uint32_t dumH2 = sb + 4 * (F_H2WH + wn * 32 + s01 * 4);
    const float C50 = -50.0f * L2E;

    #pragma unroll 1
    for (int h = 0; h < 4; ++h) {
        // ======== GEMM_P (2D): rows m0..+15, cols h*96 + wn*48 .. +47 ========
        {
            float pacc[6][4];
            #pragma unroll
            for (int a = 0; a < 6; ++a)
                #pragma unroll
                for (int b = 0; b < 4; ++b) pacc[a][b] = 0.f;
            #pragma unroll
            for (int kk = 0; kk < 2; ++kk) {
                uint32_t ah[4], al[4];
                LDSM4(ah, aG2h + 32 * kk);
                LDSM4(al, aG2l + 32 * kk);
                #pragma unroll
                for (int ntp = 0; ntp < 3; ++ntp) {
                    int n = h * 96 + wn * 48 + ntp * 16 + r8 + s2 * 8;
                    uint32_t bb = sb + 4 * (WWTH + n * 20 + kk * 8 + s01 * 4);
                    uint32_t bhr[4], blr[4];
                    LDSM4(bhr, bb);
                    LDSM4(blr, bb + 4 * (WWTL - WWTH));
                    mma3(pacc[2*ntp],   ah, al, bhr[0], bhr[1], blr[0], blr[1]);
                    mma3(pacc[2*ntp+1], ah, al, bhr[2], bhr[3], blr[2], blr[3]);
                }
            }
            if (wn == 0) {
                #pragma unroll
                for (int ntp = 0; ntp < 3; ++ntp) {
                    uint32_t h0, l0, h1, l1, h2r, l2, h3, l3;
                    pack_hl(pacc[2*ntp][0],   pacc[2*ntp][1],   h0, l0);
                    pack_hl(pacc[2*ntp][2],   pacc[2*ntp][3],   h1, l1);
                    pack_hl(pacc[2*ntp+1][0], pacc[2*ntp+1][1], h2r, l2);
                    pack_hl(pacc[2*ntp+1][2], pacc[2*ntp+1][3], h3, l3);
                    STSM4(stPH + 32 * ntp, h0, h1, h2r, h3);
                    STSM4(stPH + 32 * ntp + OFFPH, l0, l1, l2, l3);
                }
            } else {
                {
                    uint32_t h0, l0, h1, l1, h2r, l2, h3, l3;
                    pack_hl(pacc[0][0], pacc[0][1], h0, l0);
                    pack_hl(pacc[0][2], pacc[0][3], h1, l1);
                    pack_hl(pacc[1][0], pacc[1][1], h2r, l2);
                    pack_hl(pacc[1][2], pacc[1][3], h3, l3);
                    STSM4(stPH + 96, h0, h1, h2r, h3);
                    STSM4(stPH + 96 + OFFPH, l0, l1, l2, l3);
                }
                #pragma unroll
                for (int grp = 2; grp < 6; ++grp) {
                    int j0 = (grp - 2) * 8;
                    uint32_t h0, l0, h1, l1;
                    pack_hl(pacc[grp][0], pacc[grp][1], h0, l0);
                    pack_hl(pacc[grp][2], pacc[grp][3], h1, l1);
                    uint32_t ba = stCT + 4 * (j0 * 68);
                    STSM2T(ba, h0, h1);
                    STSM2T(ba + OFFCT, l0, l1);
                }
            }
        }
        __syncthreads();

        // ======== GEMM_S (2D): rows m0..+15, cols wn*64..+63 ========
        float sacc[8][4];
        #pragma unroll
        for (int a = 0; a < 8; ++a)
            #pragma unroll
            for (int b = 0; b < 4; ++b) sacc[a][b] = 0.f;
        #pragma unroll
        for (int kk = 0; kk < 2; ++kk) {
            uint32_t ah[4], al[4];
            LDSM4(ah, aPHh + 32 * kk);
            LDSM4(al, aPHh + 32 * kk + OFFPH);
            #pragma unroll
            for (int ntp = 0; ntp < 4; ++ntp) {
                int n = wn * 64 + ntp * 16 + r8 + s2 * 8;
                uint32_t bb = sb + 4 * (WPHH + n * 36 + 16 + kk * 8 + s01 * 4);
                uint32_t bhr[4], blr[4];
                LDSM4(bhr, bb);
                LDSM4(blr, bb + OFFPH);
                mma3(sacc[2*ntp],   ah, al, bhr[0], bhr[1], blr[0], blr[1]);
                mma3(sacc[2*ntp+1], ah, al, bhr[2], bhr[3], blr[2], blr[3]);
            }
        }

        // ======== softmax: e + partial sums over warp's 64 cols ========
        float ssum[2] = {0.f, 0.f};
        #pragma unroll
        for (int nt = 0; nt < 8; ++nt) {
            #pragma unroll
            for (int b = 0; b < 2; ++b) {
                int col = wn * 64 + nt * 8 + 2 * t + b;
                float4 hc = ((float4*)(smf + F_H2SW4))[col];
                float cw = fabsf(hc.w), cm = fmaxf(hc.w, 0.f);
                #pragma unroll
                for (int d = 0; d < 2; ++d) {
                    float dot = sacc[nt][d * 2 + b];
                    float h2dI = fmaf(rh2I[d][0], hc.x,
                               fmaf(rh2I[d][1], hc.y, rh2I[d][2] * hc.z));
                    float t1 = fmaf(dot, h2dI, ATTNW_SHIFT);
                    float e = ex2a(fmaf(t1, cw * rwL[d], C50));
                    ssum[d] += e;
                    sacc[nt][d * 2 + b] = (e * cm) * h2dI;
                }
            }
        }
        #pragma unroll
        for (int d = 0; d < 2; ++d) {
            float s = ssum[d];
            s += __shfl_xor_sync(0xffffffffu, s, 1);
            s += __shfl_xor_sync(0xffffffffu, s, 2);
            if (t == 0)
                smf[F_PART + (m0 + d * 8 + g) * 2 + wn] = s;
        }
        asm volatile("bar.sync %0, 64;" :: "r"(wm + 1) : "memory");
        float rs[2];
        #pragma unroll
        for (int d = 0; d < 2; ++d) {
            float2 p = *(float2*)(smf + F_PART + (m0 + d * 8 + g) * 2);
            rs[d] = rswm[d] * SQRT32 / (fmaxf(p.x + p.y, 1e-30f) * SQRT3);
        }

        // ======== GEMM_O: A = A' from sacc regs; B = Ct + H2W[h] ========
        uint32_t bb2base = (r8 < 3)
            ? sb + 4 * (F_H2WH + (h * 3 + r8) * 68 + wn * 32 + s01 * 4)
            : dumH2;
        #pragma unroll
        for (int kk = 0; kk < 4; ++kk) {
            uint32_t ah[4], al[4];
            afrag_from_acc(sacc[2*kk], sacc[2*kk+1], rs[0], rs[1], ah, al);
            #pragma unroll
            for (int ntp = 0; ntp < 2; ++ntp) {
                int n = ntp * 16 + r8 + s2 * 8;
                uint32_t bb = sb + 4 * (WCTH + n * 68 + wn * 32 + kk * 8 + s01 * 4);
                uint32_t bhr[4], blr[4];
                LDSM4(bhr, bb);
                LDSM4(blr, bb + OFFCT);
                mma3(oacc[2*ntp],   ah, al, bhr[0], bhr[1], blr[0], blr[1]);
                mma3(oacc[2*ntp+1], ah, al, bhr[2], bhr[3], blr[2], blr[3]);
            }
            {
                uint32_t b2h[2], b2l[2];
                LDSM2(b2h, bb2base + 32 * kk);
                LDSM2(b2l, bb2base + 32 * kk + OFFH2);
                mma3(oacc[4], ah, al, b2h[0], b2h[1], b2l[0], b2l[1]);
            }
        }
        __syncthreads();   // Ph/Ct reused next head
    }

    // ---- cross-wn reduction + outputs ----
    if (wn == 1) {
        #pragma unroll
        for (int d = 0; d < 2; ++d) {
            int row = m0 + d * 8 + g;
            #pragma unroll
            for (int grp = 0; grp < 5; ++grp)
                *(float2*)(smf + RBUF + row * 40 + grp * 8 + 2 * t) =
                    make_float2(oacc[grp][d * 2], oacc[grp][d * 2 + 1]);
        }
    }
    __syncthreads();
    if (wn == 0) {
        #pragma unroll
        for (int d = 0; d < 2; ++d) {
            int row = m0 + d * 8 + g;
            float* go = outg + ((size_t)loc * 128 + row) * 32;
            #pragma unroll
            for (int grp = 0; grp < 4; ++grp) {
                int col = grp * 8 + 2 * t;
                float2 r = *(float2*)(smf + RBUF + row * 40 + grp * 8 + 2 * t);
                float2 v = make_float2(oacc[grp][d*2]   + r.x + smf[F_BH + col],
                                       oacc[grp][d*2+1] + r.y + smf[F_BH + col + 1]);
                *(float2*)(go + col) = v;
            }
            if (outh) {
                float2 r4 = *(float2*)(smf + RBUF + row * 40 + 32 + 2 * t);
                float v0 = oacc[4][d*2] + r4.x;
                float v1 = oacc[4][d*2+1] + r4.y;
                float* ho = outh + ((size_t)loc * 128 + row) * 3;
                if (t == 0) { ho[0] = v0; ho[1] = v1; }
                else if (t == 1) { ho[2] = v0; }
            }
        }
    }
}

extern "C" void kernel_launch(void* const* d_in, const int* in_sizes, int n_in,
                              void* d_out, int out_size) {
    const float* g2  = (const float*)d_in[0];
    const float* h2  = (const float*)d_in[1];
    const float* sw  = (const float*)d_in[2];
    const float* wqk = (const float*)d_in[3];
    const float* wv  = (const float*)d_in[4];
    const float* wh  = (const float*)d_in[5];
    const float* bh  = (const float*)d_in[6];
    const float* weq = (const float*)d_in[7];
    const int*   msk = (const int*)d_in[8];

    int nloc = in_sizes[2] / 128;
    float* outg = (float*)d_out;
    size_t gsz = (size_t)nloc * 128 * 32;
    float* outh = ((size_t)out_size >= gsz + (size_t)nloc * 128 * 3) ? outg + gsz : nullptr;

    cudaFuncSetAttribute(rep_bf16_kernel, cudaFuncAttributeMaxDynamicSharedMemorySize, SMEM_BYTES);
    rep_bf16_kernel<<<nloc, THREADS, SMEM_BYTES>>>(g2, h2, sw, wqk, wv, wh, bh, weq, msk, outg, outh);
}